// round 12
// baseline (speedup 1.0000x reference)
#include <cuda_runtime.h>

// PCEN: s[t] = (1-c)*x[t] + c*s[t-1];  y = (x*(eps+s)^-alpha + delta)^root - delta^root
// x: [B=64, T=2048, F=128] fp32. Chunked-in-T (CT=32), float4 across F.
// 8-step warm-up (valid when c^8 <= 2^-30, runtime-checked; exact fallback).
// Depth-8 load batching. EMA states for the whole group computed BEFORE the
// 32 pcen chains, making all transcendental chains independent (MUFU duty cycle).

#define B_DIM   64
#define T_DIM   2048
#define F_DIM   128
#define F4      (F_DIM / 4)       // 32 float4 per timestep row
#define CT      32                // timesteps per chunk
#define NCHUNK  (T_DIM / CT)      // 64
#define JPB     4                 // jobs per 128-thread block
#define WFIX    8                 // fixed warm-up steps on the fast path
#define EPS_F   1e-6f

__device__ __forceinline__ float lg2_approx(float x) {
    float r; asm("lg2.approx.f32 %0, %1;" : "=f"(r) : "f"(x)); return r;
}
__device__ __forceinline__ float ex2_approx(float x) {
    float r; asm("ex2.approx.f32 %0, %1;" : "=f"(r) : "f"(x)); return r;
}
__device__ __forceinline__ float sqrt_approx(float x) {
    float r; asm("sqrt.approx.f32 %0, %1;" : "=f"(r) : "f"(x)); return r;
}

struct PcenP { float c, omc, nalpha, delta, root, droot; bool half_root; };

__device__ __forceinline__ float pcen_one(float xv, float s, const PcenP& p) {
    const float m = EPS_F + s;
    const float r = ex2_approx(p.nalpha * lg2_approx(m));   // (eps+s)^-alpha
    const float u = fmaf(xv, r, p.delta);
    const float o = p.half_root ? sqrt_approx(u)
                                : ex2_approx(p.root * lg2_approx(u));
    return o - p.droot;
}

__global__ __launch_bounds__(128, 9)
void pcen_kernel(const float4* __restrict__ x,
                 const float* __restrict__ alpha_p,
                 const float* __restrict__ delta_p,
                 const float* __restrict__ root_p,
                 const float* __restrict__ c_p,
                 float4* __restrict__ y)
{
    const int job   = blockIdx.x * JPB + threadIdx.y;   // 0..4095
    const int b     = job >> 6;                         // /NCHUNK
    const int chunk = job & (NCHUNK - 1);
    const int t0    = chunk * CT;
    const int f4    = threadIdx.x;                      // 0..31 coalesced

    PcenP p;
    p.c      = __ldg(c_p);
    p.omc    = 1.0f - p.c;
    p.nalpha = -__ldg(alpha_p);
    p.delta  = __ldg(delta_p);
    p.root   = __ldg(root_p);
    p.half_root = (p.root == 0.5f);
    p.droot  = p.half_root ? sqrt_approx(p.delta)
                           : ex2_approx(p.root * lg2_approx(p.delta));
    const float c = p.c, omc = p.omc;

    const float4* __restrict__ px = x + (size_t)(b * T_DIM + t0) * F4 + f4;
    float4*       __restrict__ py = y + (size_t)(b * T_DIM + t0) * F4 + f4;

    float sx = 0.f, sy = 0.f, sz = 0.f, sw = 0.f;

    // ---- Warm-up: bring EMA state to t0 (state truncation ~c^WFIX) ----
    const float l2c  = (c > 0.0f) ? lg2_approx(c) : -128.0f;
    const bool  fast = (c <= 0.0f) || (l2c * (float)WFIX <= -30.0f); // c^8 <= 2^-30

    if (fast) {
        if (t0 > 0) {
            const float4* pw = px - WFIX * F4;
            float4 w[WFIX];
            #pragma unroll
            for (int t = 0; t < WFIX; ++t) w[t] = __ldg(pw + t * F4);  // batched
            #pragma unroll
            for (int t = 0; t < WFIX; ++t) {
                sx = fmaf(c, sx, omc * w[t].x);
                sy = fmaf(c, sy, omc * w[t].y);
                sz = fmaf(c, sz, omc * w[t].z);
                sw = fmaf(c, sw, omc * w[t].w);
            }
        }
    } else {
        int W = t0;                                      // exact scan from t=0
        if (l2c < -1e-6f) {
            float w = -30.0f / l2c;
            if (w < (float)t0) W = (int)w + 1;
        }
        const float4* pw = px - (size_t)W * F4;
        for (int t = 0; t < W; ++t) {
            const float4 xv = __ldg(pw); pw += F4;
            sx = fmaf(c, sx, omc * xv.x);
            sy = fmaf(c, sy, omc * xv.y);
            sz = fmaf(c, sz, omc * xv.z);
            sw = fmaf(c, sw, omc * xv.w);
        }
    }

    // ---- Main chunk: 8 timesteps per iteration.
    //      Phase 1: batch 8 loads (MLP). Phase 2: run the serial EMA for all
    //      8 steps, overwriting xv[t] with its state vector. Phase 3: 32 fully
    //      independent pcen chains -> dense MUFU issue. ----
    #pragma unroll 1
    for (int i = 0; i < CT; i += 8) {
        float4 xv[8];
        #pragma unroll
        for (int t = 0; t < 8; ++t) xv[t] = __ldg(px + t * F4);
        px += 8 * F4;

        float4 sv[8];
        #pragma unroll
        for (int t = 0; t < 8; ++t) {                   // serial EMA only
            sx = fmaf(c, sx, omc * xv[t].x);
            sy = fmaf(c, sy, omc * xv[t].y);
            sz = fmaf(c, sz, omc * xv[t].z);
            sw = fmaf(c, sw, omc * xv[t].w);
            sv[t].x = sx; sv[t].y = sy; sv[t].z = sz; sv[t].w = sw;
        }

        #pragma unroll
        for (int t = 0; t < 8; ++t) {                   // independent chains
            float4 o;
            o.x = pcen_one(xv[t].x, sv[t].x, p);
            o.y = pcen_one(xv[t].y, sv[t].y, p);
            o.z = pcen_one(xv[t].z, sv[t].z, p);
            o.w = pcen_one(xv[t].w, sv[t].w, p);
            py[t * F4] = o;
        }
        py += 8 * F4;
    }
}

extern "C" void kernel_launch(void* const* d_in, const int* in_sizes, int n_in,
                              void* d_out, int out_size)
{
    const float4* x      = (const float4*)d_in[0];
    const float* alpha_p = (const float*)d_in[1];
    const float* delta_p = (const float*)d_in[2];
    const float* root_p  = (const float*)d_in[3];
    const float* coef_p  = (const float*)d_in[4];
    float4* y = (float4*)d_out;

    const int jobs   = B_DIM * NCHUNK;          // 4096
    const int blocks = jobs / JPB;              // 1024
    dim3 block(F4, JPB, 1);                     // (32, 4) = 128 threads
    pcen_kernel<<<blocks, block>>>(x, alpha_p, delta_p, root_p, coef_p, y);
}

// round 13
// speedup vs baseline: 1.3571x; 1.3571x over previous
#include <cuda_runtime.h>

// PCEN: s[t] = (1-c)*x[t] + c*s[t-1];  y = (x*(eps+s)^-alpha + delta)^root - delta^root
// x: [B=64, T=2048, F=128] fp32. Chunked-in-T (CT=32), float4 across F.
// 8-step warm-up (valid when c^8 <= 2^-30, runtime-checked; exact fallback).
// Depth-8 load batching. sqrt replaced with FMA-pipe rsqrt bit-trick + 2 Newton
// iterations (moves 1/3 of MUFU work onto the underutilized fma/alu pipes).

#define B_DIM   64
#define T_DIM   2048
#define F_DIM   128
#define F4      (F_DIM / 4)       // 32 float4 per timestep row
#define CT      32                // timesteps per chunk
#define NCHUNK  (T_DIM / CT)      // 64
#define JPB     4                 // jobs per 128-thread block
#define WFIX    8                 // fixed warm-up steps on the fast path
#define EPS_F   1e-6f

__device__ __forceinline__ float lg2_approx(float x) {
    float r; asm("lg2.approx.f32 %0, %1;" : "=f"(r) : "f"(x)); return r;
}
__device__ __forceinline__ float ex2_approx(float x) {
    float r; asm("ex2.approx.f32 %0, %1;" : "=f"(r) : "f"(x)); return r;
}
__device__ __forceinline__ float sqrt_approx(float x) {
    float r; asm("sqrt.approx.f32 %0, %1;" : "=f"(r) : "f"(x)); return r;
}
// sqrt via rsqrt bit-trick + 2 Newton steps, all on fma/alu pipes (no MUFU).
// rel err ~4e-6 after 2 iterations; valid for all positive floats.
__device__ __forceinline__ float fast_sqrt(float u) {
    u = fmaxf(u, 1.17549435e-38f);                       // keep r finite at u=0
    float r  = __int_as_float(0x5f375a86 - (__float_as_int(u) >> 1));
    const float hu = 0.5f * u;
    r = r * fmaf(-hu, r * r, 1.5f);
    r = r * fmaf(-hu, r * r, 1.5f);
    return u * r;
}
__device__ __forceinline__ void stg_cs_f4(float4* p, float4 v) {
    asm volatile("st.global.cs.v4.f32 [%0], {%1, %2, %3, %4};"
                 :: "l"(p), "f"(v.x), "f"(v.y), "f"(v.z), "f"(v.w) : "memory");
}

struct PcenP { float c, omc, nalpha, delta, root, droot; bool half_root; };

__device__ __forceinline__ float pcen_one(float xv, float s, const PcenP& p) {
    const float m = EPS_F + s;
    const float r = ex2_approx(p.nalpha * lg2_approx(m));   // (eps+s)^-alpha
    const float u = fmaf(xv, r, p.delta);
    const float o = p.half_root ? fast_sqrt(u)              // FMA-pipe sqrt
                                : ex2_approx(p.root * lg2_approx(u));
    return o - p.droot;
}

__global__ __launch_bounds__(128, 8)
void pcen_kernel(const float4* __restrict__ x,
                 const float* __restrict__ alpha_p,
                 const float* __restrict__ delta_p,
                 const float* __restrict__ root_p,
                 const float* __restrict__ c_p,
                 float4* __restrict__ y)
{
    const int job   = blockIdx.x * JPB + threadIdx.y;   // 0..4095
    const int b     = job >> 6;                         // /NCHUNK
    const int chunk = job & (NCHUNK - 1);
    const int t0    = chunk * CT;
    const int f4    = threadIdx.x;                      // 0..31 coalesced

    PcenP p;
    p.c      = __ldg(c_p);
    p.omc    = 1.0f - p.c;
    p.nalpha = -__ldg(alpha_p);
    p.delta  = __ldg(delta_p);
    p.root   = __ldg(root_p);
    p.half_root = (p.root == 0.5f);
    p.droot  = p.half_root ? sqrt_approx(p.delta)
                           : ex2_approx(p.root * lg2_approx(p.delta));
    const float c = p.c, omc = p.omc;

    const float4* __restrict__ px = x + (size_t)(b * T_DIM + t0) * F4 + f4;
    float4*       __restrict__ py = y + (size_t)(b * T_DIM + t0) * F4 + f4;

    float sx = 0.f, sy = 0.f, sz = 0.f, sw = 0.f;

    // ---- Warm-up: bring EMA state to t0 (state truncation ~c^WFIX) ----
    const float l2c  = (c > 0.0f) ? lg2_approx(c) : -128.0f;
    const bool  fast = (c <= 0.0f) || (l2c * (float)WFIX <= -30.0f); // c^8 <= 2^-30

    if (fast) {
        if (t0 > 0) {
            const float4* pw = px - WFIX * F4;
            float4 w[WFIX];
            #pragma unroll
            for (int t = 0; t < WFIX; ++t) w[t] = __ldg(pw + t * F4);  // batched
            #pragma unroll
            for (int t = 0; t < WFIX; ++t) {
                sx = fmaf(c, sx, omc * w[t].x);
                sy = fmaf(c, sy, omc * w[t].y);
                sz = fmaf(c, sz, omc * w[t].z);
                sw = fmaf(c, sw, omc * w[t].w);
            }
        }
    } else {
        int W = t0;                                      // exact scan from t=0
        if (l2c < -1e-6f) {
            float w = -30.0f / l2c;
            if (w < (float)t0) W = (int)w + 1;
        }
        const float4* pw = px - (size_t)W * F4;
        for (int t = 0; t < W; ++t) {
            const float4 xv = __ldg(pw); pw += F4;
            sx = fmaf(c, sx, omc * xv.x);
            sy = fmaf(c, sy, omc * xv.y);
            sz = fmaf(c, sz, omc * xv.z);
            sw = fmaf(c, sw, omc * xv.w);
        }
    }

    // ---- Main chunk: 8 timesteps per iteration; all 8 loads in flight ----
    #pragma unroll 1
    for (int i = 0; i < CT; i += 8) {
        float4 xv[8];
        #pragma unroll
        for (int t = 0; t < 8; ++t) xv[t] = __ldg(px + t * F4);
        px += 8 * F4;

        #pragma unroll
        for (int t = 0; t < 8; ++t) {
            sx = fmaf(c, sx, omc * xv[t].x);
            sy = fmaf(c, sy, omc * xv[t].y);
            sz = fmaf(c, sz, omc * xv[t].z);
            sw = fmaf(c, sw, omc * xv[t].w);
            float4 o;
            o.x = pcen_one(xv[t].x, sx, p);
            o.y = pcen_one(xv[t].y, sy, p);
            o.z = pcen_one(xv[t].z, sz, p);
            o.w = pcen_one(xv[t].w, sw, p);
            stg_cs_f4(py + t * F4, o);                  // store immediately
        }
        py += 8 * F4;
    }
}

extern "C" void kernel_launch(void* const* d_in, const int* in_sizes, int n_in,
                              void* d_out, int out_size)
{
    const float4* x      = (const float4*)d_in[0];
    const float* alpha_p = (const float*)d_in[1];
    const float* delta_p = (const float*)d_in[2];
    const float* root_p  = (const float*)d_in[3];
    const float* coef_p  = (const float*)d_in[4];
    float4* y = (float4*)d_out;

    const int jobs   = B_DIM * NCHUNK;          // 4096
    const int blocks = jobs / JPB;              // 1024
    dim3 block(F4, JPB, 1);                     // (32, 4) = 128 threads
    pcen_kernel<<<blocks, block>>>(x, alpha_p, delta_p, root_p, coef_p, y);
}

// round 14
// speedup vs baseline: 1.4563x; 1.0731x over previous
#include <cuda_runtime.h>

// PCEN: s[t] = (1-c)*x[t] + c*s[t-1];  y = (x*(eps+s)^-alpha + delta)^root - delta^root
// x: [B=64, T=2048, F=128] fp32. CT=16 chunks, float4 across F.
// Each THREAD processes TWO independent jobs (streams A/B) interleaved:
// 8 independent EMA/MUFU chains per thread to fill dependency-latency bubbles.
// 8-step warm-up per stream (c^8 <= 2^-30 runtime-checked; exact fallback).

#define B_DIM   64
#define T_DIM   2048
#define F_DIM   128
#define F4      (F_DIM / 4)       // 32 float4 per timestep row
#define CT      16                // timesteps per chunk
#define NCHUNK  (T_DIM / CT)      // 128
#define JPB     4                 // stream-A jobs per 128-thread block
#define HALF_JOBS (B_DIM * NCHUNK / 2)   // 4096
#define WFIX    8
#define EPS_F   1e-6f

__device__ __forceinline__ float lg2_approx(float x) {
    float r; asm("lg2.approx.f32 %0, %1;" : "=f"(r) : "f"(x)); return r;
}
__device__ __forceinline__ float ex2_approx(float x) {
    float r; asm("ex2.approx.f32 %0, %1;" : "=f"(r) : "f"(x)); return r;
}
__device__ __forceinline__ float sqrt_approx(float x) {
    float r; asm("sqrt.approx.f32 %0, %1;" : "=f"(r) : "f"(x)); return r;
}
__device__ __forceinline__ void stg_cs_f4(float4* p, float4 v) {
    asm volatile("st.global.cs.v4.f32 [%0], {%1, %2, %3, %4};"
                 :: "l"(p), "f"(v.x), "f"(v.y), "f"(v.z), "f"(v.w) : "memory");
}

struct PcenP { float c, omc, nalpha, delta, root, droot; bool half_root; };

__device__ __forceinline__ float pcen_one(float xv, float s, const PcenP& p) {
    const float m = EPS_F + s;
    const float r = ex2_approx(p.nalpha * lg2_approx(m));   // (eps+s)^-alpha
    const float u = fmaf(xv, r, p.delta);
    const float o = p.half_root ? sqrt_approx(u)
                                : ex2_approx(p.root * lg2_approx(u));
    return o - p.droot;
}

// Warm-up one stream's 4-lane EMA state (exact fallback when c -> 1).
__device__ __forceinline__ void warmup(const float4* __restrict__ px, int t0,
                                       bool fastw, float l2c, float c, float omc,
                                       float& sx, float& sy, float& sz, float& sw)
{
    if (fastw) {
        if (t0 > 0) {
            const float4* pw = px - WFIX * F4;
            float4 w[WFIX];
            #pragma unroll
            for (int t = 0; t < WFIX; ++t) w[t] = __ldg(pw + t * F4);
            #pragma unroll
            for (int t = 0; t < WFIX; ++t) {
                sx = fmaf(c, sx, omc * w[t].x);
                sy = fmaf(c, sy, omc * w[t].y);
                sz = fmaf(c, sz, omc * w[t].z);
                sw = fmaf(c, sw, omc * w[t].w);
            }
        }
    } else {
        int W = t0;
        if (l2c < -1e-6f) {
            float w = -30.0f / l2c;
            if (w < (float)t0) W = (int)w + 1;
        }
        const float4* pw = px - (size_t)W * F4;
        for (int t = 0; t < W; ++t) {
            const float4 xv = __ldg(pw); pw += F4;
            sx = fmaf(c, sx, omc * xv.x);
            sy = fmaf(c, sy, omc * xv.y);
            sz = fmaf(c, sz, omc * xv.z);
            sw = fmaf(c, sw, omc * xv.w);
        }
    }
}

__global__ __launch_bounds__(128, 7)
void pcen_kernel(const float4* __restrict__ x,
                 const float* __restrict__ alpha_p,
                 const float* __restrict__ delta_p,
                 const float* __restrict__ root_p,
                 const float* __restrict__ c_p,
                 float4* __restrict__ y)
{
    const int jobA = blockIdx.x * JPB + threadIdx.y;    // 0..4095
    const int jobB = jobA + HALF_JOBS;                  // 4096..8191
    const int f4   = threadIdx.x;                       // 0..31 coalesced

    PcenP p;
    p.c      = __ldg(c_p);
    p.omc    = 1.0f - p.c;
    p.nalpha = -__ldg(alpha_p);
    p.delta  = __ldg(delta_p);
    p.root   = __ldg(root_p);
    p.half_root = (p.root == 0.5f);
    p.droot  = p.half_root ? sqrt_approx(p.delta)
                           : ex2_approx(p.root * lg2_approx(p.delta));
    const float c = p.c, omc = p.omc;

    const int bA = jobA >> 7, chA = jobA & (NCHUNK - 1), t0A = chA * CT;
    const int bB = jobB >> 7, chB = jobB & (NCHUNK - 1), t0B = chB * CT;

    const float4* __restrict__ pxA = x + (size_t)(bA * T_DIM + t0A) * F4 + f4;
    const float4* __restrict__ pxB = x + (size_t)(bB * T_DIM + t0B) * F4 + f4;
    float4* __restrict__ pyA = y + (size_t)(bA * T_DIM + t0A) * F4 + f4;
    float4* __restrict__ pyB = y + (size_t)(bB * T_DIM + t0B) * F4 + f4;

    const float l2c   = (c > 0.0f) ? lg2_approx(c) : -128.0f;
    const bool  fastw = (c <= 0.0f) || (l2c * (float)WFIX <= -30.0f);

    float ax = 0.f, ay = 0.f, az = 0.f, aw = 0.f;
    float bx = 0.f, by = 0.f, bz = 0.f, bw = 0.f;
    warmup(pxA, t0A, fastw, l2c, c, omc, ax, ay, az, aw);
    warmup(pxB, t0B, fastw, l2c, c, omc, bx, by, bz, bw);

    // ---- Main: 4 groups of depth-4, streams A and B interleaved ----
    #pragma unroll 1
    for (int g = 0; g < CT / 4; ++g) {
        float4 xa[4], xb[4];
        #pragma unroll
        for (int t = 0; t < 4; ++t) xa[t] = __ldg(pxA + t * F4);
        #pragma unroll
        for (int t = 0; t < 4; ++t) xb[t] = __ldg(pxB + t * F4);   // 8 LDG in flight
        pxA += 4 * F4; pxB += 4 * F4;

        #pragma unroll
        for (int t = 0; t < 4; ++t) {
            // stream A step
            ax = fmaf(c, ax, omc * xa[t].x);
            ay = fmaf(c, ay, omc * xa[t].y);
            az = fmaf(c, az, omc * xa[t].z);
            aw = fmaf(c, aw, omc * xa[t].w);
            float4 oA;
            oA.x = pcen_one(xa[t].x, ax, p);
            oA.y = pcen_one(xa[t].y, ay, p);
            oA.z = pcen_one(xa[t].z, az, p);
            oA.w = pcen_one(xa[t].w, aw, p);
            stg_cs_f4(pyA + t * F4, oA);
            // stream B step (independent of A -> overlapping MUFU chains)
            bx = fmaf(c, bx, omc * xb[t].x);
            by = fmaf(c, by, omc * xb[t].y);
            bz = fmaf(c, bz, omc * xb[t].z);
            bw = fmaf(c, bw, omc * xb[t].w);
            float4 oB;
            oB.x = pcen_one(xb[t].x, bx, p);
            oB.y = pcen_one(xb[t].y, by, p);
            oB.z = pcen_one(xb[t].z, bz, p);
            oB.w = pcen_one(xb[t].w, bw, p);
            stg_cs_f4(pyB + t * F4, oB);
        }
        pyA += 4 * F4; pyB += 4 * F4;
    }
}

extern "C" void kernel_launch(void* const* d_in, const int* in_sizes, int n_in,
                              void* d_out, int out_size)
{
    const float4* x      = (const float4*)d_in[0];
    const float* alpha_p = (const float*)d_in[1];
    const float* delta_p = (const float*)d_in[2];
    const float* root_p  = (const float*)d_in[3];
    const float* coef_p  = (const float*)d_in[4];
    float4* y = (float4*)d_out;

    const int blocks = HALF_JOBS / JPB;        // 1024 (each block: 4 A-jobs + 4 B-jobs)
    dim3 block(F4, JPB, 1);                    // (32, 4) = 128 threads
    pcen_kernel<<<blocks, block>>>(x, alpha_p, delta_p, root_p, coef_p, y);
}

// round 15
// speedup vs baseline: 1.4598x; 1.0024x over previous
#include <cuda_runtime.h>

// PCEN: s[t] = (1-c)*x[t] + c*s[t-1];  y = (x*(eps+s)^-alpha + delta)^root - delta^root
// x: [B=64, T=2048, F=128] fp32. Chunked-in-T (CT=32), float4 across F (32 lanes/row).
// 8-step warm-up (valid when c^8 <= 2^-30, runtime-checked; exact fallback).
// Depth-8 load batching per loop iteration for MLP; streaming float4 stores.
// FINAL: best of 8 structural variants; all converge to the ~25us latency
// equilibrium floor (no pipe saturated: MUFU ~47%, issue ~55%, DRAM ~42%).

#define B_DIM   64
#define T_DIM   2048
#define F_DIM   128
#define F4      (F_DIM / 4)       // 32 float4 per timestep row
#define CT      32                // timesteps per chunk
#define NCHUNK  (T_DIM / CT)      // 64
#define JPB     4                 // jobs per 128-thread block
#define WFIX    8                 // fixed warm-up steps on the fast path
#define EPS_F   1e-6f

__device__ __forceinline__ float lg2_approx(float x) {
    float r; asm("lg2.approx.f32 %0, %1;" : "=f"(r) : "f"(x)); return r;
}
__device__ __forceinline__ float ex2_approx(float x) {
    float r; asm("ex2.approx.f32 %0, %1;" : "=f"(r) : "f"(x)); return r;
}
__device__ __forceinline__ float sqrt_approx(float x) {
    float r; asm("sqrt.approx.f32 %0, %1;" : "=f"(r) : "f"(x)); return r;
}
__device__ __forceinline__ void stg_cs_f4(float4* p, float4 v) {
    asm volatile("st.global.cs.v4.f32 [%0], {%1, %2, %3, %4};"
                 :: "l"(p), "f"(v.x), "f"(v.y), "f"(v.z), "f"(v.w) : "memory");
}

struct PcenP { float c, omc, nalpha, delta, root, droot; bool half_root; };

__device__ __forceinline__ float pcen_one(float xv, float s, const PcenP& p) {
    const float m = EPS_F + s;
    const float r = ex2_approx(p.nalpha * lg2_approx(m));   // (eps+s)^-alpha
    const float u = fmaf(xv, r, p.delta);
    const float o = p.half_root ? sqrt_approx(u)
                                : ex2_approx(p.root * lg2_approx(u));
    return o - p.droot;
}

__global__ __launch_bounds__(128, 8)
void pcen_kernel(const float4* __restrict__ x,
                 const float* __restrict__ alpha_p,
                 const float* __restrict__ delta_p,
                 const float* __restrict__ root_p,
                 const float* __restrict__ c_p,
                 float4* __restrict__ y)
{
    const int job   = blockIdx.x * JPB + threadIdx.y;   // 0..4095
    const int b     = job >> 6;                         // /NCHUNK
    const int chunk = job & (NCHUNK - 1);
    const int t0    = chunk * CT;
    const int f4    = threadIdx.x;                      // 0..31 coalesced

    PcenP p;
    p.c      = __ldg(c_p);
    p.omc    = 1.0f - p.c;
    p.nalpha = -__ldg(alpha_p);
    p.delta  = __ldg(delta_p);
    p.root   = __ldg(root_p);
    p.half_root = (p.root == 0.5f);
    p.droot  = p.half_root ? sqrt_approx(p.delta)
                           : ex2_approx(p.root * lg2_approx(p.delta));
    const float c = p.c, omc = p.omc;

    const float4* __restrict__ px = x + (size_t)(b * T_DIM + t0) * F4 + f4;
    float4*       __restrict__ py = y + (size_t)(b * T_DIM + t0) * F4 + f4;

    float sx = 0.f, sy = 0.f, sz = 0.f, sw = 0.f;

    // ---- Warm-up: bring EMA state to t0 (state truncation ~c^WFIX) ----
    const float l2c  = (c > 0.0f) ? lg2_approx(c) : -128.0f;
    const bool  fast = (c <= 0.0f) || (l2c * (float)WFIX <= -30.0f); // c^8 <= 2^-30

    if (fast) {
        if (t0 > 0) {
            const float4* pw = px - WFIX * F4;
            float4 w[WFIX];
            #pragma unroll
            for (int t = 0; t < WFIX; ++t) w[t] = __ldg(pw + t * F4);  // batched
            #pragma unroll
            for (int t = 0; t < WFIX; ++t) {
                sx = fmaf(c, sx, omc * w[t].x);
                sy = fmaf(c, sy, omc * w[t].y);
                sz = fmaf(c, sz, omc * w[t].z);
                sw = fmaf(c, sw, omc * w[t].w);
            }
        }
    } else {
        int W = t0;                                      // exact scan from t=0
        if (l2c < -1e-6f) {
            float w = -30.0f / l2c;
            if (w < (float)t0) W = (int)w + 1;
        }
        const float4* pw = px - (size_t)W * F4;
        for (int t = 0; t < W; ++t) {
            const float4 xv = __ldg(pw); pw += F4;
            sx = fmaf(c, sx, omc * xv.x);
            sy = fmaf(c, sy, omc * xv.y);
            sz = fmaf(c, sz, omc * xv.z);
            sw = fmaf(c, sw, omc * xv.w);
        }
    }

    // ---- Main chunk: 8 timesteps per iteration; all 8 loads in flight ----
    #pragma unroll 1
    for (int i = 0; i < CT; i += 8) {
        float4 xv[8];
        #pragma unroll
        for (int t = 0; t < 8; ++t) xv[t] = __ldg(px + t * F4);
        px += 8 * F4;

        #pragma unroll
        for (int t = 0; t < 8; ++t) {
            sx = fmaf(c, sx, omc * xv[t].x);
            sy = fmaf(c, sy, omc * xv[t].y);
            sz = fmaf(c, sz, omc * xv[t].z);
            sw = fmaf(c, sw, omc * xv[t].w);
            float4 o;
            o.x = pcen_one(xv[t].x, sx, p);
            o.y = pcen_one(xv[t].y, sy, p);
            o.z = pcen_one(xv[t].z, sz, p);
            o.w = pcen_one(xv[t].w, sw, p);
            stg_cs_f4(py + t * F4, o);                  // store immediately
        }
        py += 8 * F4;
    }
}

extern "C" void kernel_launch(void* const* d_in, const int* in_sizes, int n_in,
                              void* d_out, int out_size)
{
    const float4* x      = (const float4*)d_in[0];
    const float* alpha_p = (const float*)d_in[1];
    const float* delta_p = (const float*)d_in[2];
    const float* root_p  = (const float*)d_in[3];
    const float* coef_p  = (const float*)d_in[4];
    float4* y = (float4*)d_out;

    const int jobs   = B_DIM * NCHUNK;          // 4096
    const int blocks = jobs / JPB;              // 1024
    dim3 block(F4, JPB, 1);                     // (32, 4) = 128 threads
    pcen_kernel<<<blocks, block>>>(x, alpha_p, delta_p, root_p, coef_p, y);
}

// round 16
// speedup vs baseline: 1.4633x; 1.0024x over previous
#include <cuda_runtime.h>

// PCEN: s[t] = (1-c)*x[t] + c*s[t-1];  y = (x*(eps+s)^-alpha + delta)^root - delta^root
// x: [B=64, T=2048, F=128] fp32. Chunked-in-T (CT=32), float4 across F (32 lanes/row).
// 8-step warm-up (valid when c^8 <= 2^-30, runtime-checked; exact fallback).
// Depth-8 load batching for MLP; streaming float4 stores.
// This round: 64-thread blocks (JPB=2 -> 2048 blocks) for finer wave balance
// across 148 SMs; per-thread trace identical to the confirmed 24.9us config.

#define B_DIM   64
#define T_DIM   2048
#define F_DIM   128
#define F4      (F_DIM / 4)       // 32 float4 per timestep row
#define CT      32                // timesteps per chunk
#define NCHUNK  (T_DIM / CT)      // 64
#define JPB     2                 // jobs per 64-thread block
#define WFIX    8                 // fixed warm-up steps on the fast path
#define EPS_F   1e-6f

__device__ __forceinline__ float lg2_approx(float x) {
    float r; asm("lg2.approx.f32 %0, %1;" : "=f"(r) : "f"(x)); return r;
}
__device__ __forceinline__ float ex2_approx(float x) {
    float r; asm("ex2.approx.f32 %0, %1;" : "=f"(r) : "f"(x)); return r;
}
__device__ __forceinline__ float sqrt_approx(float x) {
    float r; asm("sqrt.approx.f32 %0, %1;" : "=f"(r) : "f"(x)); return r;
}
__device__ __forceinline__ void stg_cs_f4(float4* p, float4 v) {
    asm volatile("st.global.cs.v4.f32 [%0], {%1, %2, %3, %4};"
                 :: "l"(p), "f"(v.x), "f"(v.y), "f"(v.z), "f"(v.w) : "memory");
}

struct PcenP { float c, omc, nalpha, delta, root, droot; bool half_root; };

__device__ __forceinline__ float pcen_one(float xv, float s, const PcenP& p) {
    const float m = EPS_F + s;
    const float r = ex2_approx(p.nalpha * lg2_approx(m));   // (eps+s)^-alpha
    const float u = fmaf(xv, r, p.delta);
    const float o = p.half_root ? sqrt_approx(u)
                                : ex2_approx(p.root * lg2_approx(u));
    return o - p.droot;
}

__global__ __launch_bounds__(64, 16)
void pcen_kernel(const float4* __restrict__ x,
                 const float* __restrict__ alpha_p,
                 const float* __restrict__ delta_p,
                 const float* __restrict__ root_p,
                 const float* __restrict__ c_p,
                 float4* __restrict__ y)
{
    const int job   = blockIdx.x * JPB + threadIdx.y;   // 0..4095
    const int b     = job >> 6;                         // /NCHUNK
    const int chunk = job & (NCHUNK - 1);
    const int t0    = chunk * CT;
    const int f4    = threadIdx.x;                      // 0..31 coalesced

    PcenP p;
    p.c      = __ldg(c_p);
    p.omc    = 1.0f - p.c;
    p.nalpha = -__ldg(alpha_p);
    p.delta  = __ldg(delta_p);
    p.root   = __ldg(root_p);
    p.half_root = (p.root == 0.5f);
    p.droot  = p.half_root ? sqrt_approx(p.delta)
                           : ex2_approx(p.root * lg2_approx(p.delta));
    const float c = p.c, omc = p.omc;

    const float4* __restrict__ px = x + (size_t)(b * T_DIM + t0) * F4 + f4;
    float4*       __restrict__ py = y + (size_t)(b * T_DIM + t0) * F4 + f4;

    float sx = 0.f, sy = 0.f, sz = 0.f, sw = 0.f;

    // ---- Warm-up: bring EMA state to t0 (state truncation ~c^WFIX) ----
    const float l2c  = (c > 0.0f) ? lg2_approx(c) : -128.0f;
    const bool  fast = (c <= 0.0f) || (l2c * (float)WFIX <= -30.0f); // c^8 <= 2^-30

    if (fast) {
        if (t0 > 0) {
            const float4* pw = px - WFIX * F4;
            float4 w[WFIX];
            #pragma unroll
            for (int t = 0; t < WFIX; ++t) w[t] = __ldg(pw + t * F4);  // batched
            #pragma unroll
            for (int t = 0; t < WFIX; ++t) {
                sx = fmaf(c, sx, omc * w[t].x);
                sy = fmaf(c, sy, omc * w[t].y);
                sz = fmaf(c, sz, omc * w[t].z);
                sw = fmaf(c, sw, omc * w[t].w);
            }
        }
    } else {
        int W = t0;                                      // exact scan from t=0
        if (l2c < -1e-6f) {
            float w = -30.0f / l2c;
            if (w < (float)t0) W = (int)w + 1;
        }
        const float4* pw = px - (size_t)W * F4;
        for (int t = 0; t < W; ++t) {
            const float4 xv = __ldg(pw); pw += F4;
            sx = fmaf(c, sx, omc * xv.x);
            sy = fmaf(c, sy, omc * xv.y);
            sz = fmaf(c, sz, omc * xv.z);
            sw = fmaf(c, sw, omc * xv.w);
        }
    }

    // ---- Main chunk: 8 timesteps per iteration; all 8 loads in flight ----
    #pragma unroll 1
    for (int i = 0; i < CT; i += 8) {
        float4 xv[8];
        #pragma unroll
        for (int t = 0; t < 8; ++t) xv[t] = __ldg(px + t * F4);
        px += 8 * F4;

        #pragma unroll
        for (int t = 0; t < 8; ++t) {
            sx = fmaf(c, sx, omc * xv[t].x);
            sy = fmaf(c, sy, omc * xv[t].y);
            sz = fmaf(c, sz, omc * xv[t].z);
            sw = fmaf(c, sw, omc * xv[t].w);
            float4 o;
            o.x = pcen_one(xv[t].x, sx, p);
            o.y = pcen_one(xv[t].y, sy, p);
            o.z = pcen_one(xv[t].z, sz, p);
            o.w = pcen_one(xv[t].w, sw, p);
            stg_cs_f4(py + t * F4, o);                  // store immediately
        }
        py += 8 * F4;
    }
}

extern "C" void kernel_launch(void* const* d_in, const int* in_sizes, int n_in,
                              void* d_out, int out_size)
{
    const float4* x      = (const float4*)d_in[0];
    const float* alpha_p = (const float*)d_in[1];
    const float* delta_p = (const float*)d_in[2];
    const float* root_p  = (const float*)d_in[3];
    const float* coef_p  = (const float*)d_in[4];
    float4* y = (float4*)d_out;

    const int jobs   = B_DIM * NCHUNK;          // 4096
    const int blocks = jobs / JPB;              // 2048
    dim3 block(F4, JPB, 1);                     // (32, 2) = 64 threads
    pcen_kernel<<<blocks, block>>>(x, alpha_p, delta_p, root_p, coef_p, y);
}